// round 7
// baseline (speedup 1.0000x reference)
#include <cuda_runtime.h>
#include <cstdint>

#define Bb 2
#define Nn 2048
#define Mm 64
#define Ff 128
#define H1 64
#define H2 64
#define TILE 8          // atoms per MLP block
#define MLP_THREADS 256 // 4 pairs x 64 neurons
#define FBLK 384        // force threads per block
#define FATOMS 2        // atoms per force block (double-buffered)

// scratch (allocation-free rule: __device__ globals; zero-initialized)
__device__ float g_buf[Bb * Nn * Ff];   // input-gradient per atom  [B*N, F]
__device__ float Ei_buf[Bb * Nn];       // per-atom energy
__device__ float g_zero[Ff];            // stays all-zero (pad-neighbor source)

__device__ __forceinline__ float sigmoidf(float z) {
    return 1.f / (1.f + __expf(-z));
}

__device__ __forceinline__ void cp_async16(void* dst_smem, const void* src_gmem) {
    unsigned int d = (unsigned int)__cvta_generic_to_shared(dst_smem);
    asm volatile("cp.async.ca.shared.global [%0], [%1], 16;" :: "r"(d), "l"(src_gmem));
}

// ---------------------------------------------------------------------------
// Kernel 1: batched per-atom MLP forward + analytic input gradient.
// 256 threads / 8 atoms; 2 atoms per thread. float4 activation broadcasts;
// weights padded-transposed (stride 65, conflict-free both directions).
// ---------------------------------------------------------------------------
__global__ __launch_bounds__(MLP_THREADS) void mlp_kernel(
    const float* __restrict__ image,
    const float* __restrict__ W0,     // [H1, F]   row-major
    const float* __restrict__ W1,     // [H2, H1]  row-major
    const float* __restrict__ Wout,   // [1, H2]
    int base_atom)
{
    extern __shared__ float sm[];
    float* W0T   = sm;                      // [F][65]
    float* W1T   = W0T + Ff * 65;           // [H1][65]
    float* WoS   = W1T + H1 * 65;           // [64]
    float* xs    = WoS + 64;                // [TILE][128]
    float* h0s   = xs  + TILE * Ff;         // [TILE][64]
    float* t1s   = h0s + TILE * H1;         // [TILE][64]
    float* t0s   = t1s + TILE * H2;         // [TILE][64]
    float* ePart = t0s + TILE * H1;         // [TILE][2]

    const int t    = threadIdx.x;
    const int base = base_atom + blockIdx.x * TILE;
    const int p    = t >> 6;
    const int n    = t & 63;
    const int a0   = 2 * p, a1 = 2 * p + 1;

    for (int i = t; i < H1 * Ff; i += MLP_THREADS) {
        int r = i >> 7, f = i & 127;
        W0T[f * 65 + r] = W0[i];
    }
    for (int i = t; i < H2 * H1; i += MLP_THREADS) {
        int j = i >> 6, k = i & 63;
        W1T[k * 65 + j] = W1[i];
    }
    if (t < H2) WoS[t] = Wout[t];
    for (int i = t; i < TILE * Ff; i += MLP_THREADS)
        xs[i] = image[(size_t)base * Ff + i];
    __syncthreads();

    // phase 1
    {
        const float4* X0 = (const float4*)(xs + a0 * Ff);
        const float4* X1 = (const float4*)(xs + a1 * Ff);
        float s0a = 0.f, s0b = 0.f, s1a = 0.f, s1b = 0.f;
#pragma unroll
        for (int f4 = 0; f4 < Ff / 4; f4++) {
            float4 xa = X0[f4];
            float4 xb = X1[f4];
            const int f = f4 * 4;
            float w0 = W0T[(f + 0) * 65 + n];
            float w1 = W0T[(f + 1) * 65 + n];
            float w2 = W0T[(f + 2) * 65 + n];
            float w3 = W0T[(f + 3) * 65 + n];
            s0a = fmaf(xa.x, w0, s0a); s0b = fmaf(xa.y, w1, s0b);
            s0a = fmaf(xa.z, w2, s0a); s0b = fmaf(xa.w, w3, s0b);
            s1a = fmaf(xb.x, w0, s1a); s1b = fmaf(xb.y, w1, s1b);
            s1a = fmaf(xb.z, w2, s1a); s1b = fmaf(xb.w, w3, s1b);
        }
        h0s[a0 * 64 + n] = sigmoidf(s0a + s0b);
        h0s[a1 * 64 + n] = sigmoidf(s1a + s1b);
    }
    __syncthreads();

    // phase 2
    {
        const float4* Ha = (const float4*)(h0s + a0 * 64);
        const float4* Hb = (const float4*)(h0s + a1 * 64);
        float s0a = 0.f, s0b = 0.f, s1a = 0.f, s1b = 0.f;
#pragma unroll
        for (int k4 = 0; k4 < H1 / 4; k4++) {
            float4 ha = Ha[k4];
            float4 hb = Hb[k4];
            const int k = k4 * 4;
            float w0 = W1T[(k + 0) * 65 + n];
            float w1 = W1T[(k + 1) * 65 + n];
            float w2 = W1T[(k + 2) * 65 + n];
            float w3 = W1T[(k + 3) * 65 + n];
            s0a = fmaf(ha.x, w0, s0a); s0b = fmaf(ha.y, w1, s0b);
            s0a = fmaf(ha.z, w2, s0a); s0b = fmaf(ha.w, w3, s0b);
            s1a = fmaf(hb.x, w0, s1a); s1b = fmaf(hb.y, w1, s1b);
            s1a = fmaf(hb.z, w2, s1a); s1b = fmaf(hb.w, w3, s1b);
        }
        float wo   = WoS[n];
        float h1_0 = sigmoidf(s0a + s0b);
        float h1_1 = sigmoidf(s1a + s1b);
        t1s[a0 * 64 + n] = h1_0 * (1.f - h1_0) * wo;
        t1s[a1 * 64 + n] = h1_1 * (1.f - h1_1) * wo;
        float e0 = h1_0 * wo, e1 = h1_1 * wo;
#pragma unroll
        for (int off = 16; off > 0; off >>= 1) {
            e0 += __shfl_down_sync(0xffffffffu, e0, off);
            e1 += __shfl_down_sync(0xffffffffu, e1, off);
        }
        if ((n & 31) == 0) {
            int half = n >> 5;
            ePart[a0 * 2 + half] = e0;
            ePart[a1 * 2 + half] = e1;
        }
    }
    __syncthreads();

    // phase 3
    {
        const float4* Ta = (const float4*)(t1s + a0 * 64);
        const float4* Tb = (const float4*)(t1s + a1 * 64);
        float s0a = 0.f, s0b = 0.f, s1a = 0.f, s1b = 0.f;
#pragma unroll
        for (int j4 = 0; j4 < H2 / 4; j4++) {
            float4 ta = Ta[j4];
            float4 tb = Tb[j4];
            const int j = j4 * 4;
            float w0 = W1T[n * 65 + j + 0];
            float w1 = W1T[n * 65 + j + 1];
            float w2 = W1T[n * 65 + j + 2];
            float w3 = W1T[n * 65 + j + 3];
            s0a = fmaf(ta.x, w0, s0a); s0b = fmaf(ta.y, w1, s0b);
            s0a = fmaf(ta.z, w2, s0a); s0b = fmaf(ta.w, w3, s0b);
            s1a = fmaf(tb.x, w0, s1a); s1b = fmaf(tb.y, w1, s1b);
            s1a = fmaf(tb.z, w2, s1a); s1b = fmaf(tb.w, w3, s1b);
        }
        float h00 = h0s[a0 * 64 + n];
        float h01 = h0s[a1 * 64 + n];
        t0s[a0 * 64 + n] = h00 * (1.f - h00) * (s0a + s0b);
        t0s[a1 * 64 + n] = h01 * (1.f - h01) * (s1a + s1b);
        if (n == 0) {
            Ei_buf[base + a0] = ePart[a0 * 2] + ePart[a0 * 2 + 1];
            Ei_buf[base + a1] = ePart[a1 * 2] + ePart[a1 * 2 + 1];
        }
    }
    __syncthreads();

    // phase 4
    {
        const int f0 = n, f1 = n + 64;
        const float4* Pa = (const float4*)(t0s + a0 * 64);
        const float4* Pb = (const float4*)(t0s + a1 * 64);
        float g00 = 0.f, g01 = 0.f, g10 = 0.f, g11 = 0.f;
#pragma unroll
        for (int k4 = 0; k4 < H1 / 4; k4++) {
            float4 ta = Pa[k4];
            float4 tb = Pb[k4];
            const int k = k4 * 4;
#pragma unroll
            for (int u = 0; u < 4; u++) {
                float w0 = W0T[f0 * 65 + k + u];
                float w1 = W0T[f1 * 65 + k + u];
                float va = (u == 0) ? ta.x : (u == 1) ? ta.y : (u == 2) ? ta.z : ta.w;
                float vb = (u == 0) ? tb.x : (u == 1) ? tb.y : (u == 2) ? tb.z : tb.w;
                g00 = fmaf(va, w0, g00);
                g01 = fmaf(va, w1, g01);
                g10 = fmaf(vb, w0, g10);
                g11 = fmaf(vb, w1, g11);
            }
        }
        float* go0 = g_buf + (size_t)(base + a0) * Ff;
        float* go1 = g_buf + (size_t)(base + a1) * Ff;
        go0[f0] = g00; go0[f1] = g01;
        go1[f0] = g10; go1[f1] = g11;
    }
}

// ---------------------------------------------------------------------------
// Force helpers
// ---------------------------------------------------------------------------
__device__ __forceinline__ void gather_rows_async(
    float* dst, const int* __restrict__ nb, int b, int t)
{
    float4*       d4 = (float4*)dst;
    const float4* g4 = (const float4*)g_buf;
    const float4* z4 = (const float4*)g_zero;
    for (int i = t; i < Mm * (Ff / 4); i += FBLK) {
        int m  = i >> 5;
        int f4 = i & 31;
        int nei = __ldg(nb + m);
        const float4* src = (nei > 0)
            ? g4 + ((size_t)(b * Nn + nei - 1)) * (Ff / 4) + f4
            : z4 + f4;
        cp_async16(d4 + i, src);
    }
}

__device__ __forceinline__ void stream_atom(
    const float* __restrict__ sg, const float4* __restrict__ dp,
    float* __restrict__ out_force, int atom,
    int t, int m0, int cse, int f0, float (*wsum)[3])
{
    float A0 = 0.f, A1 = 0.f, A2 = 0.f;      // A_k holds c = (cse+k)%3
#pragma unroll
    for (int it = 0; it < 16; it++) {
        const int m = m0 + 4 * it;
        float4 v = __ldg(dp + (size_t)it * 384);
        float s0 = sg[m * Ff + f0];
        float s1 = sg[m * Ff + f0 + 1];
        float sy = (cse == 2) ? s1 : s0;
        float sz = (cse == 0) ? s0 : s1;
        A0 = fmaf(v.x, s0, A0);
        A1 = fmaf(v.y, sy, A1);
        A2 = fmaf(v.z, sz, A2);
        A0 = fmaf(v.w, s1, A0);
    }
    float c0 = (cse == 0) ? A0 : (cse == 1) ? A2 : A1;
    float c1 = (cse == 0) ? A1 : (cse == 1) ? A0 : A2;
    float c2 = (cse == 0) ? A2 : (cse == 1) ? A1 : A0;

#pragma unroll
    for (int off = 16; off > 0; off >>= 1) {
        c0 += __shfl_down_sync(0xffffffffu, c0, off);
        c1 += __shfl_down_sync(0xffffffffu, c1, off);
        c2 += __shfl_down_sync(0xffffffffu, c2, off);
    }
    const int w = t >> 5;
    if ((t & 31) == 0) { wsum[w][0] = c0; wsum[w][1] = c1; wsum[w][2] = c2; }
    __syncthreads();

    if (t < 3) {
        float s = 0.f;
#pragma unroll
        for (int w2 = 0; w2 < 12; w2++) s += wsum[w2][t];
        out_force[atom * 3 + t] = s * 1e10f;
    }
}

// ---------------------------------------------------------------------------
// Kernel 2: force, 2 atoms per CTA with double-buffered cp.async gather.
// Both gathers issued up-front as separate commit groups; atom 1's gather
// drains behind atom 0's DRAM stream -> exposed gather latency halved.
// ---------------------------------------------------------------------------
__global__ __launch_bounds__(FBLK) void force_kernel(
    const int*   __restrict__ neighbor,   // [B*N, M]
    const float* __restrict__ dfeat,      // [B*N, M, F, 3]
    float*       __restrict__ out_force,  // [B*N, 3]
    int base_atom)
{
    extern __shared__ float sg2[];           // 2 x 8192 floats (64 KB)
    __shared__ float wsum[12][3];

    const int atom0 = base_atom + blockIdx.x * FATOMS;
    const int atom1 = atom0 + 1;
    const int b     = atom0 >> 11;           // N = 2048 (both atoms same batch)
    const int t     = threadIdx.x;

    // issue both gathers (group 0 = atom0, group 1 = atom1)
    gather_rows_async(sg2,            neighbor + atom0 * Mm, b, t);
    asm volatile("cp.async.commit_group;");
    gather_rows_async(sg2 + Mm * Ff,  neighbor + atom1 * Mm, b, t);
    asm volatile("cp.async.commit_group;");

    const int r4  = t % 96;
    const int m0  = t / 96;
    const int cse = r4 % 3;
    const int f0  = (4 * r4) / 3;

    const float4* dp0 = (const float4*)(dfeat + (size_t)atom0 * (Mm * Ff * 3)) + t;
    const float4* dp1 = (const float4*)(dfeat + (size_t)atom1 * (Mm * Ff * 3)) + t;

    // wait only for atom0's gather; atom1's continues in background
    asm volatile("cp.async.wait_group 1;" ::: "memory");
    __syncthreads();
    stream_atom(sg2, dp0, out_force, atom0, t, m0, cse, f0, wsum);

    asm volatile("cp.async.wait_group 0;" ::: "memory");
    __syncthreads();
    stream_atom(sg2 + Mm * Ff, dp1, out_force, atom1, t, m0, cse, f0, wsum);
}

// ---------------------------------------------------------------------------
// Kernel 3: deterministic Etot = sum_n Ei  (double accumulation)
// ---------------------------------------------------------------------------
__global__ __launch_bounds__(256) void etot_kernel(float* __restrict__ out)
{
    const int b = blockIdx.x;
    const int t = threadIdx.x;
    __shared__ double sd[256];

    double s = 0.0;
    for (int n = t; n < Nn; n += 256) s += (double)Ei_buf[b * Nn + n];
    sd[t] = s;
    __syncthreads();
#pragma unroll
    for (int k = 128; k > 0; k >>= 1) {
        if (t < k) sd[t] += sd[t + k];
        __syncthreads();
    }
    if (t == 0) out[b] = (float)sd[0];
}

// ---------------------------------------------------------------------------
// Launch: fork-join across two streams (force(b) depends only on mlp(b)).
// ---------------------------------------------------------------------------
extern "C" void kernel_launch(void* const* d_in, const int* in_sizes, int n_in,
                              void* d_out, int out_size)
{
    const float* image    = (const float*)d_in[0];
    const float* dfeat    = (const float*)d_in[1];
    const int*   neighbor = (const int*)  d_in[2];
    const float* W0       = (const float*)d_in[5];
    const float* W1       = (const float*)d_in[6];
    const float* Wout     = (const float*)d_in[7];
    float* out = (float*)d_out;

    const int mlp_smem   = (Ff * 65 + H1 * 65 + 64 + TILE * Ff + 3 * TILE * 64 + 2 * TILE)
                         * (int)sizeof(float);
    const int force_smem = FATOMS * Mm * Ff * (int)sizeof(float);  // 64 KB

    static cudaStream_t s2 = nullptr;
    static cudaEvent_t  e0, e1, eDone;
    if (!s2) {
        cudaStreamCreateWithFlags(&s2, cudaStreamNonBlocking);
        cudaEventCreateWithFlags(&e0,    cudaEventDisableTiming);
        cudaEventCreateWithFlags(&e1,    cudaEventDisableTiming);
        cudaEventCreateWithFlags(&eDone, cudaEventDisableTiming);
        cudaFuncSetAttribute(mlp_kernel,   cudaFuncAttributeMaxDynamicSharedMemorySize, mlp_smem);
        cudaFuncSetAttribute(force_kernel, cudaFuncAttributeMaxDynamicSharedMemorySize, force_smem);
    }

    // main stream (0): mlp b0 -> e0 -> mlp b1 -> e1 -> etot -> wait eDone
    mlp_kernel<<<Nn / TILE, MLP_THREADS, mlp_smem>>>(image, W0, W1, Wout, 0);
    cudaEventRecord(e0, 0);
    mlp_kernel<<<Nn / TILE, MLP_THREADS, mlp_smem>>>(image, W0, W1, Wout, Nn);
    cudaEventRecord(e1, 0);
    etot_kernel<<<Bb, 256>>>(out);

    // side stream: force b0 after e0, force b1 after e1
    cudaStreamWaitEvent(s2, e0, 0);
    force_kernel<<<Nn / FATOMS, FBLK, force_smem, s2>>>(neighbor, dfeat, out + 2, 0);
    cudaStreamWaitEvent(s2, e1, 0);
    force_kernel<<<Nn / FATOMS, FBLK, force_smem, s2>>>(neighbor, dfeat, out + 2, Nn);
    cudaEventRecord(eDone, s2);

    cudaStreamWaitEvent(0, eDone, 0);
}

// round 8
// speedup vs baseline: 1.0553x; 1.0553x over previous
#include <cuda_runtime.h>
#include <cstdint>

#define Bb 2
#define Nn 2048
#define Mm 64
#define Ff 128
#define H1 64
#define H2 64
#define TILE 8          // atoms per MLP block
#define MLP_THREADS 256 // 4 pairs x 64 neurons
#define FBLK 512        // force threads per atom (16 warps, 4 m's each)

// scratch (allocation-free rule: __device__ globals)
__device__ float g_buf[Bb * Nn * Ff];   // input-gradient per atom  [B*N, F]
__device__ float Ei_buf[Bb * Nn];       // per-atom energy

__device__ __forceinline__ float sigmoidf(float z) {
    return 1.f / (1.f + __expf(-z));
}

// ---------------------------------------------------------------------------
// Kernel 1: batched per-atom MLP forward + analytic input gradient.
// 256 threads / 8 atoms; 2 atoms per thread. float4 activation broadcasts;
// weights padded-transposed (stride 65, conflict-free both directions).
// ---------------------------------------------------------------------------
__global__ __launch_bounds__(MLP_THREADS) void mlp_kernel(
    const float* __restrict__ image,
    const float* __restrict__ W0,     // [H1, F]   row-major
    const float* __restrict__ W1,     // [H2, H1]  row-major
    const float* __restrict__ Wout,   // [1, H2]
    int base_atom)
{
    extern __shared__ float sm[];
    float* W0T   = sm;                      // [F][65]
    float* W1T   = W0T + Ff * 65;           // [H1][65]
    float* WoS   = W1T + H1 * 65;           // [64]
    float* xs    = WoS + 64;                // [TILE][128]
    float* h0s   = xs  + TILE * Ff;         // [TILE][64]
    float* t1s   = h0s + TILE * H1;         // [TILE][64]
    float* t0s   = t1s + TILE * H2;         // [TILE][64]
    float* ePart = t0s + TILE * H1;         // [TILE][2]

    const int t    = threadIdx.x;
    const int base = base_atom + blockIdx.x * TILE;
    const int p    = t >> 6;
    const int n    = t & 63;
    const int a0   = 2 * p, a1 = 2 * p + 1;

    for (int i = t; i < H1 * Ff; i += MLP_THREADS) {
        int r = i >> 7, f = i & 127;
        W0T[f * 65 + r] = W0[i];
    }
    for (int i = t; i < H2 * H1; i += MLP_THREADS) {
        int j = i >> 6, k = i & 63;
        W1T[k * 65 + j] = W1[i];
    }
    if (t < H2) WoS[t] = Wout[t];
    for (int i = t; i < TILE * Ff; i += MLP_THREADS)
        xs[i] = image[(size_t)base * Ff + i];
    __syncthreads();

    // phase 1: h0 = sigmoid(x @ W0^T)
    {
        const float4* X0 = (const float4*)(xs + a0 * Ff);
        const float4* X1 = (const float4*)(xs + a1 * Ff);
        float s0a = 0.f, s0b = 0.f, s1a = 0.f, s1b = 0.f;
#pragma unroll
        for (int f4 = 0; f4 < Ff / 4; f4++) {
            float4 xa = X0[f4];
            float4 xb = X1[f4];
            const int f = f4 * 4;
            float w0 = W0T[(f + 0) * 65 + n];
            float w1 = W0T[(f + 1) * 65 + n];
            float w2 = W0T[(f + 2) * 65 + n];
            float w3 = W0T[(f + 3) * 65 + n];
            s0a = fmaf(xa.x, w0, s0a); s0b = fmaf(xa.y, w1, s0b);
            s0a = fmaf(xa.z, w2, s0a); s0b = fmaf(xa.w, w3, s0b);
            s1a = fmaf(xb.x, w0, s1a); s1b = fmaf(xb.y, w1, s1b);
            s1a = fmaf(xb.z, w2, s1a); s1b = fmaf(xb.w, w3, s1b);
        }
        h0s[a0 * 64 + n] = sigmoidf(s0a + s0b);
        h0s[a1 * 64 + n] = sigmoidf(s1a + s1b);
    }
    __syncthreads();

    // phase 2: h1, t1 = h1(1-h1)*Wout, Ei partials
    {
        const float4* Ha = (const float4*)(h0s + a0 * 64);
        const float4* Hb = (const float4*)(h0s + a1 * 64);
        float s0a = 0.f, s0b = 0.f, s1a = 0.f, s1b = 0.f;
#pragma unroll
        for (int k4 = 0; k4 < H1 / 4; k4++) {
            float4 ha = Ha[k4];
            float4 hb = Hb[k4];
            const int k = k4 * 4;
            float w0 = W1T[(k + 0) * 65 + n];
            float w1 = W1T[(k + 1) * 65 + n];
            float w2 = W1T[(k + 2) * 65 + n];
            float w3 = W1T[(k + 3) * 65 + n];
            s0a = fmaf(ha.x, w0, s0a); s0b = fmaf(ha.y, w1, s0b);
            s0a = fmaf(ha.z, w2, s0a); s0b = fmaf(ha.w, w3, s0b);
            s1a = fmaf(hb.x, w0, s1a); s1b = fmaf(hb.y, w1, s1b);
            s1a = fmaf(hb.z, w2, s1a); s1b = fmaf(hb.w, w3, s1b);
        }
        float wo   = WoS[n];
        float h1_0 = sigmoidf(s0a + s0b);
        float h1_1 = sigmoidf(s1a + s1b);
        t1s[a0 * 64 + n] = h1_0 * (1.f - h1_0) * wo;
        t1s[a1 * 64 + n] = h1_1 * (1.f - h1_1) * wo;
        float e0 = h1_0 * wo, e1 = h1_1 * wo;
#pragma unroll
        for (int off = 16; off > 0; off >>= 1) {
            e0 += __shfl_down_sync(0xffffffffu, e0, off);
            e1 += __shfl_down_sync(0xffffffffu, e1, off);
        }
        if ((n & 31) == 0) {
            int half = n >> 5;
            ePart[a0 * 2 + half] = e0;
            ePart[a1 * 2 + half] = e1;
        }
    }
    __syncthreads();

    // phase 3: g1 = t1 @ W1 ; t0 = h0(1-h0)*g1
    {
        const float4* Ta = (const float4*)(t1s + a0 * 64);
        const float4* Tb = (const float4*)(t1s + a1 * 64);
        float s0a = 0.f, s0b = 0.f, s1a = 0.f, s1b = 0.f;
#pragma unroll
        for (int j4 = 0; j4 < H2 / 4; j4++) {
            float4 ta = Ta[j4];
            float4 tb = Tb[j4];
            const int j = j4 * 4;
            float w0 = W1T[n * 65 + j + 0];
            float w1 = W1T[n * 65 + j + 1];
            float w2 = W1T[n * 65 + j + 2];
            float w3 = W1T[n * 65 + j + 3];
            s0a = fmaf(ta.x, w0, s0a); s0b = fmaf(ta.y, w1, s0b);
            s0a = fmaf(ta.z, w2, s0a); s0b = fmaf(ta.w, w3, s0b);
            s1a = fmaf(tb.x, w0, s1a); s1b = fmaf(tb.y, w1, s1b);
            s1a = fmaf(tb.z, w2, s1a); s1b = fmaf(tb.w, w3, s1b);
        }
        float h00 = h0s[a0 * 64 + n];
        float h01 = h0s[a1 * 64 + n];
        t0s[a0 * 64 + n] = h00 * (1.f - h00) * (s0a + s0b);
        t0s[a1 * 64 + n] = h01 * (1.f - h01) * (s1a + s1b);
        if (n == 0) {
            Ei_buf[base + a0] = ePart[a0 * 2] + ePart[a0 * 2 + 1];
            Ei_buf[base + a1] = ePart[a1 * 2] + ePart[a1 * 2 + 1];
        }
    }
    __syncthreads();

    // phase 4: g[f] = sum_k t0[k] * W0[k][f]
    {
        const int f0 = n, f1 = n + 64;
        const float4* Pa = (const float4*)(t0s + a0 * 64);
        const float4* Pb = (const float4*)(t0s + a1 * 64);
        float g00 = 0.f, g01 = 0.f, g10 = 0.f, g11 = 0.f;
#pragma unroll
        for (int k4 = 0; k4 < H1 / 4; k4++) {
            float4 ta = Pa[k4];
            float4 tb = Pb[k4];
            const int k = k4 * 4;
#pragma unroll
            for (int u = 0; u < 4; u++) {
                float w0 = W0T[f0 * 65 + k + u];
                float w1 = W0T[f1 * 65 + k + u];
                float va = (u == 0) ? ta.x : (u == 1) ? ta.y : (u == 2) ? ta.z : ta.w;
                float vb = (u == 0) ? tb.x : (u == 1) ? tb.y : (u == 2) ? tb.z : tb.w;
                g00 = fmaf(va, w0, g00);
                g01 = fmaf(va, w1, g01);
                g10 = fmaf(vb, w0, g10);
                g11 = fmaf(vb, w1, g11);
            }
        }
        float* go0 = g_buf + (size_t)(base + a0) * Ff;
        float* go1 = g_buf + (size_t)(base + a1) * Ff;
        go0[f0] = g00; go0[f1] = g01;
        go1[f0] = g10; go1[f1] = g11;
    }
}

// ---------------------------------------------------------------------------
// Kernel 2: force, barrier-free warp-per-m design.
// One 512-thread block per atom; warp w handles m = w, w+16, w+32, w+48.
// g rows read directly from L1/L2 (no smem staging, no gather barrier) while
// the warp streams its contiguous 1536B dfeat slices with LDG.128.
// dfeat element o = 4*r4+e of slice m maps to f=(4r4+e)/3, c=(4r4+e)%3 with
// r4 = it*32+lane; cse=r4%3, f0=4r4/3 precomputed per it.
// ---------------------------------------------------------------------------
__global__ __launch_bounds__(FBLK) void force_kernel(
    const int*   __restrict__ neighbor,   // [B*N, M]
    const float* __restrict__ dfeat,      // [B*N, M, F, 3]
    float*       __restrict__ out_force,  // [B*N, 3]
    int base_atom)
{
    const int atom = base_atom + blockIdx.x;
    const int b    = atom >> 11;            // N = 2048
    const int t    = threadIdx.x;
    const int w    = t >> 5;                // warp 0..15
    const int lane = t & 31;

    __shared__ float wsum[16][3];

    // per-it lane constants
    int cse[3], fo[3];
#pragma unroll
    for (int it = 0; it < 3; it++) {
        int r4 = it * 32 + lane;
        cse[it] = r4 % 3;
        fo[it]  = (4 * r4) / 3;
    }

    const float*  gB  = g_buf + (size_t)(b * Nn) * Ff;
    const float4* dA  = (const float4*)dfeat + (size_t)atom * (Mm * Ff * 3 / 4);
    const int*    nb  = neighbor + atom * Mm;

    float c0 = 0.f, c1 = 0.f, c2 = 0.f;

#pragma unroll
    for (int k = 0; k < 4; k++) {
        const int m   = w + 16 * k;
        const int nei = __ldg(nb + m);
        const float msk = (nei > 0) ? 1e10f : 0.f;      // fold FORCE_SCALE here
        const float* gr = gB + (size_t)max(nei - 1, 0) * Ff;
        const float4* dm = dA + m * 96;

#pragma unroll
        for (int it = 0; it < 3; it++) {
            float4 v = __ldg(dm + it * 32 + lane);
            float s0 = __ldg(gr + fo[it])     * msk;
            float s1 = __ldg(gr + fo[it] + 1) * msk;
            int   cs = cse[it];
            float sy = (cs == 2) ? s1 : s0;
            float sz = (cs == 0) ? s0 : s1;
            float p0 = fmaf(v.x, s0, v.w * s1);   // channel cs
            float p1 = v.y * sy;                  // channel (cs+1)%3
            float p2 = v.z * sz;                  // channel (cs+2)%3
            c0 += (cs == 0) ? p0 : (cs == 1) ? p2 : p1;
            c1 += (cs == 0) ? p1 : (cs == 1) ? p0 : p2;
            c2 += (cs == 0) ? p2 : (cs == 1) ? p1 : p0;
        }
    }

#pragma unroll
    for (int off = 16; off > 0; off >>= 1) {
        c0 += __shfl_down_sync(0xffffffffu, c0, off);
        c1 += __shfl_down_sync(0xffffffffu, c1, off);
        c2 += __shfl_down_sync(0xffffffffu, c2, off);
    }
    if (lane == 0) { wsum[w][0] = c0; wsum[w][1] = c1; wsum[w][2] = c2; }
    __syncthreads();

    if (t < 3) {
        float s = 0.f;
#pragma unroll
        for (int w2 = 0; w2 < 16; w2++) s += wsum[w2][t];
        out_force[atom * 3 + t] = s;
    }
}

// ---------------------------------------------------------------------------
// Kernel 3: deterministic Etot = sum_n Ei  (double accumulation)
// ---------------------------------------------------------------------------
__global__ __launch_bounds__(256) void etot_kernel(float* __restrict__ out)
{
    const int b = blockIdx.x;
    const int t = threadIdx.x;
    __shared__ double sd[256];

    double s = 0.0;
    for (int n = t; n < Nn; n += 256) s += (double)Ei_buf[b * Nn + n];
    sd[t] = s;
    __syncthreads();
#pragma unroll
    for (int k = 128; k > 0; k >>= 1) {
        if (t < k) sd[t] += sd[t + k];
        __syncthreads();
    }
    if (t == 0) out[b] = (float)sd[0];
}

// ---------------------------------------------------------------------------
// Launch: fork-join across two streams (force(b) depends only on mlp(b)).
// ---------------------------------------------------------------------------
extern "C" void kernel_launch(void* const* d_in, const int* in_sizes, int n_in,
                              void* d_out, int out_size)
{
    const float* image    = (const float*)d_in[0];
    const float* dfeat    = (const float*)d_in[1];
    const int*   neighbor = (const int*)  d_in[2];
    const float* W0       = (const float*)d_in[5];
    const float* W1       = (const float*)d_in[6];
    const float* Wout     = (const float*)d_in[7];
    float* out = (float*)d_out;

    const int mlp_smem = (Ff * 65 + H1 * 65 + 64 + TILE * Ff + 3 * TILE * 64 + 2 * TILE)
                       * (int)sizeof(float);

    static cudaStream_t s2 = nullptr;
    static cudaEvent_t  e0, e1, eDone;
    if (!s2) {
        cudaStreamCreateWithFlags(&s2, cudaStreamNonBlocking);
        cudaEventCreateWithFlags(&e0,    cudaEventDisableTiming);
        cudaEventCreateWithFlags(&e1,    cudaEventDisableTiming);
        cudaEventCreateWithFlags(&eDone, cudaEventDisableTiming);
        cudaFuncSetAttribute(mlp_kernel, cudaFuncAttributeMaxDynamicSharedMemorySize, mlp_smem);
    }

    // main stream (0): mlp b0 -> e0 -> mlp b1 -> e1 -> etot -> wait eDone
    mlp_kernel<<<Nn / TILE, MLP_THREADS, mlp_smem>>>(image, W0, W1, Wout, 0);
    cudaEventRecord(e0, 0);
    mlp_kernel<<<Nn / TILE, MLP_THREADS, mlp_smem>>>(image, W0, W1, Wout, Nn);
    cudaEventRecord(e1, 0);
    etot_kernel<<<Bb, 256>>>(out);

    // side stream: force b0 after e0, force b1 after e1
    cudaStreamWaitEvent(s2, e0, 0);
    force_kernel<<<Nn, FBLK, 0, s2>>>(neighbor, dfeat, out + 2, 0);
    cudaStreamWaitEvent(s2, e1, 0);
    force_kernel<<<Nn, FBLK, 0, s2>>>(neighbor, dfeat, out + 2, Nn);
    cudaEventRecord(eDone, s2);

    cudaStreamWaitEvent(0, eDone, 0);
}

// round 9
// speedup vs baseline: 1.1651x; 1.1040x over previous
#include <cuda_runtime.h>
#include <cstdint>

#define Bb 2
#define Nn 2048
#define Mm 64
#define Ff 128
#define H1 64
#define H2 64
#define TILE 8          // atoms per MLP block
#define MLP_THREADS 256 // 4 pairs x 64 neurons
#define FBLK 384        // force threads per atom block

// scratch (allocation-free rule: __device__ globals)
__device__ float g_buf[Bb * Nn * Ff];   // input-gradient per atom  [B*N, F]
__device__ float Ei_buf[Bb * Nn];       // per-atom energy

__device__ __forceinline__ float sigmoidf(float z) {
    return 1.f / (1.f + __expf(-z));
}

// ---------------------------------------------------------------------------
// Kernel 1: batched per-atom MLP forward + analytic input gradient.
// 256 threads / 8 atoms; 2 atoms per thread. float4 activation broadcasts;
// weights padded-transposed (stride 65, conflict-free both directions).
// ---------------------------------------------------------------------------
__global__ __launch_bounds__(MLP_THREADS) void mlp_kernel(
    const float* __restrict__ image,
    const float* __restrict__ W0,     // [H1, F]   row-major
    const float* __restrict__ W1,     // [H2, H1]  row-major
    const float* __restrict__ Wout,   // [1, H2]
    int base_atom)
{
    extern __shared__ float sm[];
    float* W0T   = sm;                      // [F][65]
    float* W1T   = W0T + Ff * 65;           // [H1][65]
    float* WoS   = W1T + H1 * 65;           // [64]
    float* xs    = WoS + 64;                // [TILE][128]
    float* h0s   = xs  + TILE * Ff;         // [TILE][64]
    float* t1s   = h0s + TILE * H1;         // [TILE][64]
    float* t0s   = t1s + TILE * H2;         // [TILE][64]
    float* ePart = t0s + TILE * H1;         // [TILE][2]

    const int t    = threadIdx.x;
    const int base = base_atom + blockIdx.x * TILE;
    const int p    = t >> 6;
    const int n    = t & 63;
    const int a0   = 2 * p, a1 = 2 * p + 1;

    for (int i = t; i < H1 * Ff; i += MLP_THREADS) {
        int r = i >> 7, f = i & 127;
        W0T[f * 65 + r] = W0[i];
    }
    for (int i = t; i < H2 * H1; i += MLP_THREADS) {
        int j = i >> 6, k = i & 63;
        W1T[k * 65 + j] = W1[i];
    }
    if (t < H2) WoS[t] = Wout[t];
    for (int i = t; i < TILE * Ff; i += MLP_THREADS)
        xs[i] = image[(size_t)base * Ff + i];
    __syncthreads();

    // phase 1: h0 = sigmoid(x @ W0^T)
    {
        const float4* X0 = (const float4*)(xs + a0 * Ff);
        const float4* X1 = (const float4*)(xs + a1 * Ff);
        float s0a = 0.f, s0b = 0.f, s1a = 0.f, s1b = 0.f;
#pragma unroll
        for (int f4 = 0; f4 < Ff / 4; f4++) {
            float4 xa = X0[f4];
            float4 xb = X1[f4];
            const int f = f4 * 4;
            float w0 = W0T[(f + 0) * 65 + n];
            float w1 = W0T[(f + 1) * 65 + n];
            float w2 = W0T[(f + 2) * 65 + n];
            float w3 = W0T[(f + 3) * 65 + n];
            s0a = fmaf(xa.x, w0, s0a); s0b = fmaf(xa.y, w1, s0b);
            s0a = fmaf(xa.z, w2, s0a); s0b = fmaf(xa.w, w3, s0b);
            s1a = fmaf(xb.x, w0, s1a); s1b = fmaf(xb.y, w1, s1b);
            s1a = fmaf(xb.z, w2, s1a); s1b = fmaf(xb.w, w3, s1b);
        }
        h0s[a0 * 64 + n] = sigmoidf(s0a + s0b);
        h0s[a1 * 64 + n] = sigmoidf(s1a + s1b);
    }
    __syncthreads();

    // phase 2: h1, t1 = h1(1-h1)*Wout, Ei partials
    {
        const float4* Ha = (const float4*)(h0s + a0 * 64);
        const float4* Hb = (const float4*)(h0s + a1 * 64);
        float s0a = 0.f, s0b = 0.f, s1a = 0.f, s1b = 0.f;
#pragma unroll
        for (int k4 = 0; k4 < H1 / 4; k4++) {
            float4 ha = Ha[k4];
            float4 hb = Hb[k4];
            const int k = k4 * 4;
            float w0 = W1T[(k + 0) * 65 + n];
            float w1 = W1T[(k + 1) * 65 + n];
            float w2 = W1T[(k + 2) * 65 + n];
            float w3 = W1T[(k + 3) * 65 + n];
            s0a = fmaf(ha.x, w0, s0a); s0b = fmaf(ha.y, w1, s0b);
            s0a = fmaf(ha.z, w2, s0a); s0b = fmaf(ha.w, w3, s0b);
            s1a = fmaf(hb.x, w0, s1a); s1b = fmaf(hb.y, w1, s1b);
            s1a = fmaf(hb.z, w2, s1a); s1b = fmaf(hb.w, w3, s1b);
        }
        float wo   = WoS[n];
        float h1_0 = sigmoidf(s0a + s0b);
        float h1_1 = sigmoidf(s1a + s1b);
        t1s[a0 * 64 + n] = h1_0 * (1.f - h1_0) * wo;
        t1s[a1 * 64 + n] = h1_1 * (1.f - h1_1) * wo;
        float e0 = h1_0 * wo, e1 = h1_1 * wo;
#pragma unroll
        for (int off = 16; off > 0; off >>= 1) {
            e0 += __shfl_down_sync(0xffffffffu, e0, off);
            e1 += __shfl_down_sync(0xffffffffu, e1, off);
        }
        if ((n & 31) == 0) {
            int half = n >> 5;
            ePart[a0 * 2 + half] = e0;
            ePart[a1 * 2 + half] = e1;
        }
    }
    __syncthreads();

    // phase 3: g1 = t1 @ W1 ; t0 = h0(1-h0)*g1
    {
        const float4* Ta = (const float4*)(t1s + a0 * 64);
        const float4* Tb = (const float4*)(t1s + a1 * 64);
        float s0a = 0.f, s0b = 0.f, s1a = 0.f, s1b = 0.f;
#pragma unroll
        for (int j4 = 0; j4 < H2 / 4; j4++) {
            float4 ta = Ta[j4];
            float4 tb = Tb[j4];
            const int j = j4 * 4;
            float w0 = W1T[n * 65 + j + 0];
            float w1 = W1T[n * 65 + j + 1];
            float w2 = W1T[n * 65 + j + 2];
            float w3 = W1T[n * 65 + j + 3];
            s0a = fmaf(ta.x, w0, s0a); s0b = fmaf(ta.y, w1, s0b);
            s0a = fmaf(ta.z, w2, s0a); s0b = fmaf(ta.w, w3, s0b);
            s1a = fmaf(tb.x, w0, s1a); s1b = fmaf(tb.y, w1, s1b);
            s1a = fmaf(tb.z, w2, s1a); s1b = fmaf(tb.w, w3, s1b);
        }
        float h00 = h0s[a0 * 64 + n];
        float h01 = h0s[a1 * 64 + n];
        t0s[a0 * 64 + n] = h00 * (1.f - h00) * (s0a + s0b);
        t0s[a1 * 64 + n] = h01 * (1.f - h01) * (s1a + s1b);
        if (n == 0) {
            Ei_buf[base + a0] = ePart[a0 * 2] + ePart[a0 * 2 + 1];
            Ei_buf[base + a1] = ePart[a1 * 2] + ePart[a1 * 2 + 1];
        }
    }
    __syncthreads();

    // phase 4: g[f] = sum_k t0[k] * W0[k][f]
    {
        const int f0 = n, f1 = n + 64;
        const float4* Pa = (const float4*)(t0s + a0 * 64);
        const float4* Pb = (const float4*)(t0s + a1 * 64);
        float g00 = 0.f, g01 = 0.f, g10 = 0.f, g11 = 0.f;
#pragma unroll
        for (int k4 = 0; k4 < H1 / 4; k4++) {
            float4 ta = Pa[k4];
            float4 tb = Pb[k4];
            const int k = k4 * 4;
#pragma unroll
            for (int u = 0; u < 4; u++) {
                float w0 = W0T[f0 * 65 + k + u];
                float w1 = W0T[f1 * 65 + k + u];
                float va = (u == 0) ? ta.x : (u == 1) ? ta.y : (u == 2) ? ta.z : ta.w;
                float vb = (u == 0) ? tb.x : (u == 1) ? tb.y : (u == 2) ? tb.z : tb.w;
                g00 = fmaf(va, w0, g00);
                g01 = fmaf(va, w1, g01);
                g10 = fmaf(vb, w0, g10);
                g11 = fmaf(vb, w1, g11);
            }
        }
        float* go0 = g_buf + (size_t)(base + a0) * Ff;
        float* go1 = g_buf + (size_t)(base + a1) * Ff;
        go0[f0] = g00; go0[f1] = g01;
        go1[f0] = g10; go1[f1] = g11;
    }
}

// ---------------------------------------------------------------------------
// Kernel 2: force (best-measured shape: monolithic per-atom, 384 threads,
// 32 KB smem gather, LDG.128 stream of the contiguous 96 KB dfeat slice).
// ---------------------------------------------------------------------------
__global__ __launch_bounds__(FBLK) void force_kernel(
    const int*   __restrict__ neighbor,   // [B*N, M]
    const float* __restrict__ dfeat,      // [B*N, M, F, 3]
    float*       __restrict__ out_force,  // [B*N, 3]
    int base_atom)
{
    const int atom = base_atom + blockIdx.x;
    const int b    = atom >> 11;            // N = 2048
    const int t    = threadIdx.x;

    __shared__ float sg[Mm * Ff];            // 32 KB gathered+masked g rows
    __shared__ float wsum[12][3];

    {
        float4*       sg4 = (float4*)sg;
        const float4* g4  = (const float4*)g_buf;
        for (int i = t; i < Mm * (Ff / 4); i += FBLK) {
            int m  = i >> 5;                 // 32 float4 per row
            int f4 = i & 31;
            int nei = __ldg(neighbor + atom * Mm + m);
            sg4[i] = (nei > 0)
                   ? g4[((size_t)(b * Nn + nei - 1)) * (Ff / 4) + f4]
                   : make_float4(0.f, 0.f, 0.f, 0.f);
        }
    }
    __syncthreads();

    const int r4  = t % 96;                  // loop-invariant per thread
    const int m0  = t / 96;                  // 0..3
    const int cse = r4 % 3;
    const int f0  = (4 * r4) / 3;            // 0..126

    const float4* dp = (const float4*)(dfeat + (size_t)atom * (Mm * Ff * 3)) + t;

    float A0 = 0.f, A1 = 0.f, A2 = 0.f;      // A_k holds c = (cse+k)%3
#pragma unroll
    for (int it = 0; it < 16; it++) {
        const int m = m0 + 4 * it;
        float4 v = __ldg(dp + (size_t)it * 384);
        float s0 = sg[m * Ff + f0];
        float s1 = sg[m * Ff + f0 + 1];
        float sy = (cse == 2) ? s1 : s0;
        float sz = (cse == 0) ? s0 : s1;
        A0 = fmaf(v.x, s0, A0);
        A1 = fmaf(v.y, sy, A1);
        A2 = fmaf(v.z, sz, A2);
        A0 = fmaf(v.w, s1, A0);
    }
    float c0 = (cse == 0) ? A0 : (cse == 1) ? A2 : A1;
    float c1 = (cse == 0) ? A1 : (cse == 1) ? A0 : A2;
    float c2 = (cse == 0) ? A2 : (cse == 1) ? A1 : A0;

#pragma unroll
    for (int off = 16; off > 0; off >>= 1) {
        c0 += __shfl_down_sync(0xffffffffu, c0, off);
        c1 += __shfl_down_sync(0xffffffffu, c1, off);
        c2 += __shfl_down_sync(0xffffffffu, c2, off);
    }
    const int w = t >> 5;
    if ((t & 31) == 0) { wsum[w][0] = c0; wsum[w][1] = c1; wsum[w][2] = c2; }
    __syncthreads();

    if (t < 3) {
        float s = 0.f;
#pragma unroll
        for (int w2 = 0; w2 < 12; w2++) s += wsum[w2][t];
        out_force[atom * 3 + t] = s * 1e10f;
    }
}

// ---------------------------------------------------------------------------
// Kernel 3: deterministic Etot = sum_n Ei  (double accumulation)
// ---------------------------------------------------------------------------
__global__ __launch_bounds__(256) void etot_kernel(float* __restrict__ out)
{
    const int b = blockIdx.x;
    const int t = threadIdx.x;
    __shared__ double sd[256];

    double s = 0.0;
    for (int n = t; n < Nn; n += 256) s += (double)Ei_buf[b * Nn + n];
    sd[t] = s;
    __syncthreads();
#pragma unroll
    for (int k = 128; k > 0; k >>= 1) {
        if (t < k) sd[t] += sd[t + k];
        __syncthreads();
    }
    if (t == 0) out[b] = (float)sd[0];
}

// ---------------------------------------------------------------------------
// Launch: fork-join with the two force launches on SEPARATE side streams so
// force_b1 backfills force_b0's draining wave (recovers single-big-launch
// behavior) while mlp_b1 + etot hide behind force_b0.
// ---------------------------------------------------------------------------
extern "C" void kernel_launch(void* const* d_in, const int* in_sizes, int n_in,
                              void* d_out, int out_size)
{
    const float* image    = (const float*)d_in[0];
    const float* dfeat    = (const float*)d_in[1];
    const int*   neighbor = (const int*)  d_in[2];
    const float* W0       = (const float*)d_in[5];
    const float* W1       = (const float*)d_in[6];
    const float* Wout     = (const float*)d_in[7];
    float* out = (float*)d_out;

    const int mlp_smem = (Ff * 65 + H1 * 65 + 64 + TILE * Ff + 3 * TILE * 64 + 2 * TILE)
                       * (int)sizeof(float);

    static cudaStream_t s2 = nullptr, s3 = nullptr;
    static cudaEvent_t  e0, e1, eD0, eD1;
    if (!s2) {
        cudaStreamCreateWithFlags(&s2, cudaStreamNonBlocking);
        cudaStreamCreateWithFlags(&s3, cudaStreamNonBlocking);
        cudaEventCreateWithFlags(&e0,  cudaEventDisableTiming);
        cudaEventCreateWithFlags(&e1,  cudaEventDisableTiming);
        cudaEventCreateWithFlags(&eD0, cudaEventDisableTiming);
        cudaEventCreateWithFlags(&eD1, cudaEventDisableTiming);
        cudaFuncSetAttribute(mlp_kernel, cudaFuncAttributeMaxDynamicSharedMemorySize, mlp_smem);
    }

    // main stream (0): mlp b0 -> e0 -> mlp b1 -> e1 -> etot -> join
    mlp_kernel<<<Nn / TILE, MLP_THREADS, mlp_smem>>>(image, W0, W1, Wout, 0);
    cudaEventRecord(e0, 0);
    mlp_kernel<<<Nn / TILE, MLP_THREADS, mlp_smem>>>(image, W0, W1, Wout, Nn);
    cudaEventRecord(e1, 0);
    etot_kernel<<<Bb, 256>>>(out);

    // side stream s2: force b0 after mlp b0
    cudaStreamWaitEvent(s2, e0, 0);
    force_kernel<<<Nn, FBLK, 0, s2>>>(neighbor, dfeat, out + 2, 0);
    cudaEventRecord(eD0, s2);

    // side stream s3: force b1 after mlp b1 (backfills force b0's tail)
    cudaStreamWaitEvent(s3, e1, 0);
    force_kernel<<<Nn, FBLK, 0, s3>>>(neighbor, dfeat, out + 2, Nn);
    cudaEventRecord(eD1, s3);

    cudaStreamWaitEvent(0, eD0, 0);
    cudaStreamWaitEvent(0, eD1, 0);
}

// round 10
// speedup vs baseline: 1.2169x; 1.0445x over previous
#include <cuda_runtime.h>
#include <cstdint>

#define Bb 2
#define Nn 2048
#define Mm 64
#define Ff 128
#define H1 64
#define H2 64
#define TILE 8          // atoms per MLP block
#define MLP_THREADS 256 // 4 pairs x 64 neurons
#define FBLK 384        // force threads per atom block

// scratch (allocation-free rule: __device__ globals; zero-initialized)
__device__ float g_buf[Bb * Nn * Ff];   // input-gradient per atom  [B*N, F]
__device__ float Ei_buf[Bb * Nn];       // per-atom energy
__device__ float g_zero[Ff];            // stays all-zero (pad-neighbor source)

__device__ __forceinline__ float sigmoidf(float z) {
    return 1.f / (1.f + __expf(-z));
}

__device__ __forceinline__ void cp_async16(void* dst_smem, const void* src_gmem) {
    unsigned int d = (unsigned int)__cvta_generic_to_shared(dst_smem);
    asm volatile("cp.async.ca.shared.global [%0], [%1], 16;" :: "r"(d), "l"(src_gmem));
}

// ---------------------------------------------------------------------------
// Kernel 1: batched per-atom MLP forward + analytic input gradient.
// 256 threads / 8 atoms; 2 atoms per thread. float4 activation broadcasts;
// weights padded-transposed (stride 65, conflict-free both directions).
// ---------------------------------------------------------------------------
__global__ __launch_bounds__(MLP_THREADS) void mlp_kernel(
    const float* __restrict__ image,
    const float* __restrict__ W0,     // [H1, F]   row-major
    const float* __restrict__ W1,     // [H2, H1]  row-major
    const float* __restrict__ Wout,   // [1, H2]
    int base_atom)
{
    extern __shared__ float sm[];
    float* W0T   = sm;                      // [F][65]
    float* W1T   = W0T + Ff * 65;           // [H1][65]
    float* WoS   = W1T + H1 * 65;           // [64]
    float* xs    = WoS + 64;                // [TILE][128]
    float* h0s   = xs  + TILE * Ff;         // [TILE][64]
    float* t1s   = h0s + TILE * H1;         // [TILE][64]
    float* t0s   = t1s + TILE * H2;         // [TILE][64]
    float* ePart = t0s + TILE * H1;         // [TILE][2]

    const int t    = threadIdx.x;
    const int base = base_atom + blockIdx.x * TILE;
    const int p    = t >> 6;
    const int n    = t & 63;
    const int a0   = 2 * p, a1 = 2 * p + 1;

    for (int i = t; i < H1 * Ff; i += MLP_THREADS) {
        int r = i >> 7, f = i & 127;
        W0T[f * 65 + r] = W0[i];
    }
    for (int i = t; i < H2 * H1; i += MLP_THREADS) {
        int j = i >> 6, k = i & 63;
        W1T[k * 65 + j] = W1[i];
    }
    if (t < H2) WoS[t] = Wout[t];
    for (int i = t; i < TILE * Ff; i += MLP_THREADS)
        xs[i] = image[(size_t)base * Ff + i];
    __syncthreads();

    // phase 1: h0 = sigmoid(x @ W0^T)
    {
        const float4* X0 = (const float4*)(xs + a0 * Ff);
        const float4* X1 = (const float4*)(xs + a1 * Ff);
        float s0a = 0.f, s0b = 0.f, s1a = 0.f, s1b = 0.f;
#pragma unroll
        for (int f4 = 0; f4 < Ff / 4; f4++) {
            float4 xa = X0[f4];
            float4 xb = X1[f4];
            const int f = f4 * 4;
            float w0 = W0T[(f + 0) * 65 + n];
            float w1 = W0T[(f + 1) * 65 + n];
            float w2 = W0T[(f + 2) * 65 + n];
            float w3 = W0T[(f + 3) * 65 + n];
            s0a = fmaf(xa.x, w0, s0a); s0b = fmaf(xa.y, w1, s0b);
            s0a = fmaf(xa.z, w2, s0a); s0b = fmaf(xa.w, w3, s0b);
            s1a = fmaf(xb.x, w0, s1a); s1b = fmaf(xb.y, w1, s1b);
            s1a = fmaf(xb.z, w2, s1a); s1b = fmaf(xb.w, w3, s1b);
        }
        h0s[a0 * 64 + n] = sigmoidf(s0a + s0b);
        h0s[a1 * 64 + n] = sigmoidf(s1a + s1b);
    }
    __syncthreads();

    // phase 2: h1, t1 = h1(1-h1)*Wout, Ei partials
    {
        const float4* Ha = (const float4*)(h0s + a0 * 64);
        const float4* Hb = (const float4*)(h0s + a1 * 64);
        float s0a = 0.f, s0b = 0.f, s1a = 0.f, s1b = 0.f;
#pragma unroll
        for (int k4 = 0; k4 < H1 / 4; k4++) {
            float4 ha = Ha[k4];
            float4 hb = Hb[k4];
            const int k = k4 * 4;
            float w0 = W1T[(k + 0) * 65 + n];
            float w1 = W1T[(k + 1) * 65 + n];
            float w2 = W1T[(k + 2) * 65 + n];
            float w3 = W1T[(k + 3) * 65 + n];
            s0a = fmaf(ha.x, w0, s0a); s0b = fmaf(ha.y, w1, s0b);
            s0a = fmaf(ha.z, w2, s0a); s0b = fmaf(ha.w, w3, s0b);
            s1a = fmaf(hb.x, w0, s1a); s1b = fmaf(hb.y, w1, s1b);
            s1a = fmaf(hb.z, w2, s1a); s1b = fmaf(hb.w, w3, s1b);
        }
        float wo   = WoS[n];
        float h1_0 = sigmoidf(s0a + s0b);
        float h1_1 = sigmoidf(s1a + s1b);
        t1s[a0 * 64 + n] = h1_0 * (1.f - h1_0) * wo;
        t1s[a1 * 64 + n] = h1_1 * (1.f - h1_1) * wo;
        float e0 = h1_0 * wo, e1 = h1_1 * wo;
#pragma unroll
        for (int off = 16; off > 0; off >>= 1) {
            e0 += __shfl_down_sync(0xffffffffu, e0, off);
            e1 += __shfl_down_sync(0xffffffffu, e1, off);
        }
        if ((n & 31) == 0) {
            int half = n >> 5;
            ePart[a0 * 2 + half] = e0;
            ePart[a1 * 2 + half] = e1;
        }
    }
    __syncthreads();

    // phase 3: g1 = t1 @ W1 ; t0 = h0(1-h0)*g1
    {
        const float4* Ta = (const float4*)(t1s + a0 * 64);
        const float4* Tb = (const float4*)(t1s + a1 * 64);
        float s0a = 0.f, s0b = 0.f, s1a = 0.f, s1b = 0.f;
#pragma unroll
        for (int j4 = 0; j4 < H2 / 4; j4++) {
            float4 ta = Ta[j4];
            float4 tb = Tb[j4];
            const int j = j4 * 4;
            float w0 = W1T[n * 65 + j + 0];
            float w1 = W1T[n * 65 + j + 1];
            float w2 = W1T[n * 65 + j + 2];
            float w3 = W1T[n * 65 + j + 3];
            s0a = fmaf(ta.x, w0, s0a); s0b = fmaf(ta.y, w1, s0b);
            s0a = fmaf(ta.z, w2, s0a); s0b = fmaf(ta.w, w3, s0b);
            s1a = fmaf(tb.x, w0, s1a); s1b = fmaf(tb.y, w1, s1b);
            s1a = fmaf(tb.z, w2, s1a); s1b = fmaf(tb.w, w3, s1b);
        }
        float h00 = h0s[a0 * 64 + n];
        float h01 = h0s[a1 * 64 + n];
        t0s[a0 * 64 + n] = h00 * (1.f - h00) * (s0a + s0b);
        t0s[a1 * 64 + n] = h01 * (1.f - h01) * (s1a + s1b);
        if (n == 0) {
            Ei_buf[base + a0] = ePart[a0 * 2] + ePart[a0 * 2 + 1];
            Ei_buf[base + a1] = ePart[a1 * 2] + ePart[a1 * 2 + 1];
        }
    }
    __syncthreads();

    // phase 4: g[f] = sum_k t0[k] * W0[k][f]
    {
        const int f0 = n, f1 = n + 64;
        const float4* Pa = (const float4*)(t0s + a0 * 64);
        const float4* Pb = (const float4*)(t0s + a1 * 64);
        float g00 = 0.f, g01 = 0.f, g10 = 0.f, g11 = 0.f;
#pragma unroll
        for (int k4 = 0; k4 < H1 / 4; k4++) {
            float4 ta = Pa[k4];
            float4 tb = Pb[k4];
            const int k = k4 * 4;
#pragma unroll
            for (int u = 0; u < 4; u++) {
                float w0 = W0T[f0 * 65 + k + u];
                float w1 = W0T[f1 * 65 + k + u];
                float va = (u == 0) ? ta.x : (u == 1) ? ta.y : (u == 2) ? ta.z : ta.w;
                float vb = (u == 0) ? tb.x : (u == 1) ? tb.y : (u == 2) ? tb.z : tb.w;
                g00 = fmaf(va, w0, g00);
                g01 = fmaf(va, w1, g01);
                g10 = fmaf(vb, w0, g10);
                g11 = fmaf(vb, w1, g11);
            }
        }
        float* go0 = g_buf + (size_t)(base + a0) * Ff;
        float* go1 = g_buf + (size_t)(base + a1) * Ff;
        go0[f0] = g00; go0[f1] = g01;
        go1[f0] = g10; go1[f1] = g11;
    }
}

// ---------------------------------------------------------------------------
// Kernel 2: force — proven 384-thread/32KB shape, but the gather is issued as
// 4 independent cp.async commit groups (16 rows each) into quarters of the
// same buffer, and the stream loop consumes chunk-by-chunk with progressive
// wait_group. Streaming starts after 1/4 of the gather; chunks 1-3 drain
// behind DRAM traffic. Same occupancy, same smem, no extra registers.
// ---------------------------------------------------------------------------
__global__ __launch_bounds__(FBLK) void force_kernel(
    const int*   __restrict__ neighbor,   // [B*N, M]
    const float* __restrict__ dfeat,      // [B*N, M, F, 3]
    float*       __restrict__ out_force,  // [B*N, 3]
    int base_atom)
{
    const int atom = base_atom + blockIdx.x;
    const int b    = atom >> 11;            // N = 2048
    const int t    = threadIdx.x;

    __shared__ float sg[Mm * Ff];            // 32 KB gathered+masked g rows
    __shared__ float wsum[12][3];

    // ---- issue 4 gather chunks (16 rows = 512 float4 each) ----
    {
        float4*       sg4 = (float4*)sg;
        const float4* g4  = (const float4*)g_buf;
        const float4* z4  = (const float4*)g_zero;
        const int*    nb  = neighbor + atom * Mm;
#pragma unroll
        for (int c = 0; c < 4; c++) {
            for (int i = c * 512 + t; i < (c + 1) * 512; i += FBLK) {
                int m  = i >> 5;             // row 0..63
                int f4 = i & 31;
                int nei = __ldg(nb + m);
                const float4* src = (nei > 0)
                    ? g4 + ((size_t)(b * Nn + nei - 1)) * (Ff / 4) + f4
                    : z4 + f4;
                cp_async16(sg4 + i, src);
            }
            asm volatile("cp.async.commit_group;");
        }
    }

    const int r4  = t % 96;                  // loop-invariant per thread
    const int m0  = t / 96;                  // 0..3
    const int cse = r4 % 3;
    const int f0  = (4 * r4) / 3;            // 0..126

    const float4* dp = (const float4*)(dfeat + (size_t)atom * (Mm * Ff * 3)) + t;

    float A0 = 0.f, A1 = 0.f, A2 = 0.f;      // A_k holds c = (cse+k)%3
#pragma unroll
    for (int c = 0; c < 4; c++) {
        // chunk c (rows 16c..16c+15) ready when <= 3-c groups pending
        if (c == 0)      asm volatile("cp.async.wait_group 3;" ::: "memory");
        else if (c == 1) asm volatile("cp.async.wait_group 2;" ::: "memory");
        else if (c == 2) asm volatile("cp.async.wait_group 1;" ::: "memory");
        else             asm volatile("cp.async.wait_group 0;" ::: "memory");
        __syncthreads();
#pragma unroll
        for (int q = 0; q < 4; q++) {
            const int it = c * 4 + q;
            const int m  = m0 + 4 * it;      // m in [16c, 16c+16)
            float4 v = __ldg(dp + (size_t)it * 384);
            float s0 = sg[m * Ff + f0];
            float s1 = sg[m * Ff + f0 + 1];
            float sy = (cse == 2) ? s1 : s0;
            float sz = (cse == 0) ? s0 : s1;
            A0 = fmaf(v.x, s0, A0);
            A1 = fmaf(v.y, sy, A1);
            A2 = fmaf(v.z, sz, A2);
            A0 = fmaf(v.w, s1, A0);
        }
    }
    float c0 = (cse == 0) ? A0 : (cse == 1) ? A2 : A1;
    float c1 = (cse == 0) ? A1 : (cse == 1) ? A0 : A2;
    float c2 = (cse == 0) ? A2 : (cse == 1) ? A1 : A0;

#pragma unroll
    for (int off = 16; off > 0; off >>= 1) {
        c0 += __shfl_down_sync(0xffffffffu, c0, off);
        c1 += __shfl_down_sync(0xffffffffu, c1, off);
        c2 += __shfl_down_sync(0xffffffffu, c2, off);
    }
    const int w = t >> 5;
    if ((t & 31) == 0) { wsum[w][0] = c0; wsum[w][1] = c1; wsum[w][2] = c2; }
    __syncthreads();

    if (t < 3) {
        float s = 0.f;
#pragma unroll
        for (int w2 = 0; w2 < 12; w2++) s += wsum[w2][t];
        out_force[atom * 3 + t] = s * 1e10f;
    }
}

// ---------------------------------------------------------------------------
// Kernel 3: deterministic Etot = sum_n Ei  (double accumulation)
// ---------------------------------------------------------------------------
__global__ __launch_bounds__(256) void etot_kernel(float* __restrict__ out)
{
    const int b = blockIdx.x;
    const int t = threadIdx.x;
    __shared__ double sd[256];

    double s = 0.0;
    for (int n = t; n < Nn; n += 256) s += (double)Ei_buf[b * Nn + n];
    sd[t] = s;
    __syncthreads();
#pragma unroll
    for (int k = 128; k > 0; k >>= 1) {
        if (t < k) sd[t] += sd[t + k];
        __syncthreads();
    }
    if (t == 0) out[b] = (float)sd[0];
}

// ---------------------------------------------------------------------------
// Launch: fork-join; force launches on separate side streams (b1 backfills
// b0's draining wave); mlp_b1 + etot hide behind force_b0.
// ---------------------------------------------------------------------------
extern "C" void kernel_launch(void* const* d_in, const int* in_sizes, int n_in,
                              void* d_out, int out_size)
{
    const float* image    = (const float*)d_in[0];
    const float* dfeat    = (const float*)d_in[1];
    const int*   neighbor = (const int*)  d_in[2];
    const float* W0       = (const float*)d_in[5];
    const float* W1       = (const float*)d_in[6];
    const float* Wout     = (const float*)d_in[7];
    float* out = (float*)d_out;

    const int mlp_smem = (Ff * 65 + H1 * 65 + 64 + TILE * Ff + 3 * TILE * 64 + 2 * TILE)
                       * (int)sizeof(float);

    static cudaStream_t s2 = nullptr, s3 = nullptr;
    static cudaEvent_t  e0, e1, eD0, eD1;
    if (!s2) {
        cudaStreamCreateWithFlags(&s2, cudaStreamNonBlocking);
        cudaStreamCreateWithFlags(&s3, cudaStreamNonBlocking);
        cudaEventCreateWithFlags(&e0,  cudaEventDisableTiming);
        cudaEventCreateWithFlags(&e1,  cudaEventDisableTiming);
        cudaEventCreateWithFlags(&eD0, cudaEventDisableTiming);
        cudaEventCreateWithFlags(&eD1, cudaEventDisableTiming);
        cudaFuncSetAttribute(mlp_kernel, cudaFuncAttributeMaxDynamicSharedMemorySize, mlp_smem);
    }

    // main stream (0): mlp b0 -> e0 -> mlp b1 -> e1 -> etot -> join
    mlp_kernel<<<Nn / TILE, MLP_THREADS, mlp_smem>>>(image, W0, W1, Wout, 0);
    cudaEventRecord(e0, 0);
    mlp_kernel<<<Nn / TILE, MLP_THREADS, mlp_smem>>>(image, W0, W1, Wout, Nn);
    cudaEventRecord(e1, 0);
    etot_kernel<<<Bb, 256>>>(out);

    // side stream s2: force b0 after mlp b0
    cudaStreamWaitEvent(s2, e0, 0);
    force_kernel<<<Nn, FBLK, 0, s2>>>(neighbor, dfeat, out + 2, 0);
    cudaEventRecord(eD0, s2);

    // side stream s3: force b1 after mlp b1 (backfills force b0's tail)
    cudaStreamWaitEvent(s3, e1, 0);
    force_kernel<<<Nn, FBLK, 0, s3>>>(neighbor, dfeat, out + 2, Nn);
    cudaEventRecord(eD1, s3);

    cudaStreamWaitEvent(0, eD0, 0);
    cudaStreamWaitEvent(0, eD1, 0);
}